// round 12
// baseline (speedup 1.0000x reference)
#include <cuda_runtime.h>
#include <cstdint>

#define L_LEN   65536
#define L_MASK  (L_LEN - 1)
#define CIN     8
#define COUT    8
#define FS      4
#define TPB     128
#define TILE    1024       // positions per block (256 per warp)
#define ROWW    260        // per-warp row: 256 + 4 halo floats (16B-aligned)
#define WAVE    592        // 148 SMs * 4 resident blocks = one wave

// ---- packed f32x2 helpers (Blackwell sm_100a+) ------------------------------
__device__ __forceinline__ float2 ffma2(float2 a, float2 b, float2 c) {
    float2 d;
    asm("fma.rn.f32x2 %0, %1, %2, %3;"
        : "=l"(reinterpret_cast<unsigned long long&>(d))
        : "l"(reinterpret_cast<const unsigned long long&>(a)),
          "l"(reinterpret_cast<const unsigned long long&>(b)),
          "l"(reinterpret_cast<const unsigned long long&>(c)));
    return d;
}

__device__ __forceinline__ float2 dup2(float x) {
    float2 d;
    asm("mov.b64 %0, {%1, %1};"
        : "=l"(reinterpret_cast<unsigned long long&>(d))
        : "f"(x));
    return d;
}

__device__ __forceinline__ void prefetch_l2(const void* p) {
    asm volatile("prefetch.global.L2 [%0];" :: "l"(p));
}

// ----------------------------------------------------------------------------
// out[b, co, l] = bias[co] + sum_{ci,k} x[b, ci, (l+k) mod L] * W[co, ci, k]
//
// R11 (warp-autonomous, best: 47.6us) + ONE change: cross-wave L2 prefetch.
// Before staging its own tile, each block issues prefetch.global.L2 hints for
// the tile of blockIdx.x + WAVE (the block that will run on this SM slot in
// the next wave). 2 waves x 19.5MB fits easily in 126MB L2, so next-wave
// prologue LDGs hit L2 (~240 cyc) instead of DRAM (~600 cyc).
// Each warp owns a private SMEM region + weight copy, sync = __syncwarp only.
// ----------------------------------------------------------------------------
__global__ __launch_bounds__(TPB, 4)
void conv_pbc_kernel(const float* __restrict__ x,
                     const float* __restrict__ W,
                     const float* __restrict__ bias,
                     float* __restrict__ out)
{
    __shared__ float  xs[4][CIN][ROWW];          // per-warp x regions
    __shared__ float2 w2s[4][CIN][FS][COUT / 2]; // per-warp weight copies
    __shared__ float2 b2s[4][COUT / 2];          // per-warp bias copies

    const int t   = threadIdx.x;
    const int w   = t >> 5;
    const int lid = t & 31;

    // ---- cross-wave L2 prefetch: tile of block (blockIdx.x + WAVE) ----
    {
        const int nb = blockIdx.x + WAVE;
        if (nb < 4096) {
            const int   bn    = nb >> 6;
            const int   basen = (nb & 63) << 10;
            const float* __restrict__ xbn =
                x + (size_t)bn * CIN * L_LEN + basen;
            // 8 ci x 32 lines of 128B = the full 32KB tile; 2 hints/thread
            const int ci = t >> 4;            // 0..7
            const int ln = t & 15;            // 0..15
            const float* p = xbn + (size_t)ci * L_LEN + ln * 32;
            prefetch_l2(p);
            prefetch_l2(p + 16 * 32);         // lines 16..31
        }
    }

    const int b    = blockIdx.x >> 6;                        // 64 chunks/batch
    const int base = ((blockIdx.x & 63) << 10) + (w << 8);   // warp's 256 pos

    const float* __restrict__ xb = x + (size_t)b * CIN * L_LEN;

    // ---- stage x: 16 coalesced LDG.128 + halo, all issued before any STS ----
    float4 va[CIN], vb[CIN], vh;
    #pragma unroll
    for (int ci = 0; ci < CIN; ++ci) {
        const float4* __restrict__ xc4 =
            reinterpret_cast<const float4*>(xb + (size_t)ci * L_LEN + base);
        va[ci] = xc4[lid];
        vb[ci] = xc4[lid + 32];
    }
    if (lid < CIN)   // halo: 4 floats past the warp region, circular, aligned
        vh = *reinterpret_cast<const float4*>(
            xb + (size_t)lid * L_LEN + ((base + 256) & L_MASK));

    #pragma unroll
    for (int ci = 0; ci < CIN; ++ci) {
        *reinterpret_cast<float4*>(&xs[w][ci][4 * lid])       = va[ci];
        *reinterpret_cast<float4*>(&xs[w][ci][128 + 4 * lid]) = vb[ci];
    }
    if (lid < CIN)
        *reinterpret_cast<float4*>(&xs[w][lid][256]) = vh;

    // ---- per-warp weights/bias (after x STS to keep the register peak) ----
    {
        const int ci = (lid >> 2) & 7;
        const int k  = lid & 3;
        #pragma unroll
        for (int cp = 0; cp < 4; ++cp)
            w2s[w][ci][k][cp] =
                make_float2(W[(2 * cp)     * CIN * FS + ci * FS + k],
                            W[(2 * cp + 1) * CIN * FS + ci * FS + k]);
        if (lid < COUT / 2)
            b2s[w][lid] = make_float2(bias[2 * lid], bias[2 * lid + 1]);
    }
    __syncwarp();                                // the ONLY sync in the kernel

    // ---- accumulators: acc[bundle][q][cp], init = bias ----
    float2 acc[2][4][COUT / 2];
    {
        const float2 c0 = b2s[w][0], c1 = b2s[w][1],
                     c2 = b2s[w][2], c3 = b2s[w][3];
        #pragma unroll
        for (int j = 0; j < 2; ++j)
            #pragma unroll
            for (int q = 0; q < 4; ++q) {
                acc[j][q][0] = c0; acc[j][q][1] = c1;
                acc[j][q][2] = c2; acc[j][q][3] = c3;
            }
    }

    // ---- monolithic compute from SMEM ----
    #pragma unroll
    for (int ci = 0; ci < CIN; ++ci) {
        float2 wv[FS][COUT / 2];
        #pragma unroll
        for (int k = 0; k < FS; ++k)
            #pragma unroll
            for (int cp = 0; cp < 4; ++cp)
                wv[k][cp] = w2s[w][ci][k][cp];

        float xw[2][8];
        {
            const float4 a0 = *reinterpret_cast<const float4*>(&xs[w][ci][4 * lid]);
            const float4 a1 = *reinterpret_cast<const float4*>(&xs[w][ci][4 * lid + 4]);
            const float4 b0 = *reinterpret_cast<const float4*>(&xs[w][ci][128 + 4 * lid]);
            const float4 b1 = *reinterpret_cast<const float4*>(&xs[w][ci][128 + 4 * lid + 4]);
            xw[0][0] = a0.x; xw[0][1] = a0.y; xw[0][2] = a0.z; xw[0][3] = a0.w;
            xw[0][4] = a1.x; xw[0][5] = a1.y; xw[0][6] = a1.z; xw[0][7] = a1.w;
            xw[1][0] = b0.x; xw[1][1] = b0.y; xw[1][2] = b0.z; xw[1][3] = b0.w;
            xw[1][4] = b1.x; xw[1][5] = b1.y; xw[1][6] = b1.z; xw[1][7] = b1.w;
        }

        #pragma unroll
        for (int j = 0; j < 2; ++j) {
            #pragma unroll
            for (int i = 0; i < 7; ++i) {
                const float2 xk = dup2(xw[j][i]);
                #pragma unroll
                for (int k = 0; k < FS; ++k) {
                    const int q = i - k;
                    if (q >= 0 && q < 4) {
                        #pragma unroll
                        for (int cp = 0; cp < 4; ++cp)
                            acc[j][q][cp] = ffma2(wv[k][cp], xk, acc[j][q][cp]);
                    }
                }
            }
        }
    }

    // ---- epilogue: warp-coalesced STG.128 per (co, bundle) ----
    float* __restrict__ ob = out + (size_t)b * COUT * L_LEN + base + 4 * lid;
    #pragma unroll
    for (int cp = 0; cp < 4; ++cp) {
        #pragma unroll
        for (int j = 0; j < 2; ++j) {
            float4 v;
            v.x = acc[j][0][cp].x; v.y = acc[j][1][cp].x;
            v.z = acc[j][2][cp].x; v.w = acc[j][3][cp].x;
            *reinterpret_cast<float4*>(ob + (size_t)(2 * cp) * L_LEN + 128 * j) = v;
            v.x = acc[j][0][cp].y; v.y = acc[j][1][cp].y;
            v.z = acc[j][2][cp].y; v.w = acc[j][3][cp].y;
            *reinterpret_cast<float4*>(ob + (size_t)(2 * cp + 1) * L_LEN + 128 * j) = v;
        }
    }
}

extern "C" void kernel_launch(void* const* d_in, const int* in_sizes, int n_in,
                              void* d_out, int out_size)
{
    const float* x    = (const float*)d_in[0];  // (64, 8, 65536)
    const float* W    = (const float*)d_in[1];  // (8, 8, 4)
    const float* bias = (const float*)d_in[2];  // (8,)
    float* out        = (float*)d_out;          // (64, 8, 65536)

    // 64 batches * 64 chunks (1024 positions, 256 per warp) = 4096 blocks
    conv_pbc_kernel<<<64 * (L_LEN / TILE), TPB>>>(x, W, bias, out);
}

// round 13
// speedup vs baseline: 1.1719x; 1.1719x over previous
#include <cuda_runtime.h>
#include <cstdint>

#define L_LEN   65536
#define L_MASK  (L_LEN - 1)
#define CIN     8
#define COUT    8
#define FS      4
#define TPB     128
#define TILE    1024       // positions per block (256 per warp)
#define ROWW    260        // per-warp row: 256 + 4 halo floats (16B-aligned)

// ---- packed f32x2 helpers (Blackwell sm_100a+) ------------------------------
__device__ __forceinline__ float2 ffma2(float2 a, float2 b, float2 c) {
    float2 d;
    asm("fma.rn.f32x2 %0, %1, %2, %3;"
        : "=l"(reinterpret_cast<unsigned long long&>(d))
        : "l"(reinterpret_cast<const unsigned long long&>(a)),
          "l"(reinterpret_cast<const unsigned long long&>(b)),
          "l"(reinterpret_cast<const unsigned long long&>(c)));
    return d;
}

__device__ __forceinline__ float2 dup2(float x) {
    float2 d;
    asm("mov.b64 %0, {%1, %1};"
        : "=l"(reinterpret_cast<unsigned long long&>(d))
        : "f"(x));
    return d;
}

// ----------------------------------------------------------------------------
// out[b, co, l] = bias[co] + sum_{ci,k} x[b, ci, (l+k) mod L] * W[co, ci, k]
//
// R11 (warp-autonomous, best: 47.6us) with ONE change: weight loads in the
// compute loop are vectorized LDS.128 (2 per k) instead of 8 scalar LDS.64.
// R11's profile showed L1/shared (68.8%) as the hottest pipe — the 16
// LDS.64 weight reloads per ci per thread were the binding MIO load. This
// cuts per-warp MIO instructions by ~30%. (R12's L2 prefetch reverted: it
// added LSU ops to the already-binding L1tex queue and regressed.)
// Each warp owns a private SMEM region + weight copy; sync = __syncwarp only.
// ----------------------------------------------------------------------------
__global__ __launch_bounds__(TPB, 4)
void conv_pbc_kernel(const float* __restrict__ x,
                     const float* __restrict__ W,
                     const float* __restrict__ bias,
                     float* __restrict__ out)
{
    __shared__ float xs[4][CIN][ROWW];                        // per-warp x
    __shared__ __align__(16) float2 w2s[4][CIN][FS][COUT / 2];// per-warp W
    __shared__ float2 b2s[4][COUT / 2];                       // per-warp bias

    const int t   = threadIdx.x;
    const int w   = t >> 5;
    const int lid = t & 31;

    const int b    = blockIdx.x >> 6;                        // 64 chunks/batch
    const int base = ((blockIdx.x & 63) << 10) + (w << 8);   // warp's 256 pos

    const float* __restrict__ xb = x + (size_t)b * CIN * L_LEN;

    // ---- stage x: 16 coalesced LDG.128 + halo, all issued before any STS ----
    float4 va[CIN], vb[CIN], vh;
    #pragma unroll
    for (int ci = 0; ci < CIN; ++ci) {
        const float4* __restrict__ xc4 =
            reinterpret_cast<const float4*>(xb + (size_t)ci * L_LEN + base);
        va[ci] = xc4[lid];
        vb[ci] = xc4[lid + 32];
    }
    if (lid < CIN)   // halo: 4 floats past the warp region, circular, aligned
        vh = *reinterpret_cast<const float4*>(
            xb + (size_t)lid * L_LEN + ((base + 256) & L_MASK));

    #pragma unroll
    for (int ci = 0; ci < CIN; ++ci) {
        *reinterpret_cast<float4*>(&xs[w][ci][4 * lid])       = va[ci];
        *reinterpret_cast<float4*>(&xs[w][ci][128 + 4 * lid]) = vb[ci];
    }
    if (lid < CIN)
        *reinterpret_cast<float4*>(&xs[w][lid][256]) = vh;

    // ---- per-warp weights/bias (after x STS to keep the register peak) ----
    {
        const int ci = (lid >> 2) & 7;
        const int k  = lid & 3;
        #pragma unroll
        for (int cp = 0; cp < 4; ++cp)
            w2s[w][ci][k][cp] =
                make_float2(W[(2 * cp)     * CIN * FS + ci * FS + k],
                            W[(2 * cp + 1) * CIN * FS + ci * FS + k]);
        if (lid < COUT / 2)
            b2s[w][lid] = make_float2(bias[2 * lid], bias[2 * lid + 1]);
    }
    __syncwarp();                                // the ONLY sync in the kernel

    // ---- accumulators: acc[bundle][q][cp], init = bias ----
    float2 acc[2][4][COUT / 2];
    {
        const float2 c0 = b2s[w][0], c1 = b2s[w][1],
                     c2 = b2s[w][2], c3 = b2s[w][3];
        #pragma unroll
        for (int j = 0; j < 2; ++j)
            #pragma unroll
            for (int q = 0; q < 4; ++q) {
                acc[j][q][0] = c0; acc[j][q][1] = c1;
                acc[j][q][2] = c2; acc[j][q][3] = c3;
            }
    }

    // ---- monolithic compute from SMEM ----
    #pragma unroll
    for (int ci = 0; ci < CIN; ++ci) {
        // packed weights for this ci: 2 broadcast LDS.128 per k (was 8 LDS.64)
        float2 wv[FS][COUT / 2];
        #pragma unroll
        for (int k = 0; k < FS; ++k) {
            const float4 wa = *reinterpret_cast<const float4*>(&w2s[w][ci][k][0]);
            const float4 wb = *reinterpret_cast<const float4*>(&w2s[w][ci][k][2]);
            wv[k][0] = make_float2(wa.x, wa.y);
            wv[k][1] = make_float2(wa.z, wa.w);
            wv[k][2] = make_float2(wb.x, wb.y);
            wv[k][3] = make_float2(wb.z, wb.w);
        }

        float xw[2][8];
        {
            const float4 a0 = *reinterpret_cast<const float4*>(&xs[w][ci][4 * lid]);
            const float4 a1 = *reinterpret_cast<const float4*>(&xs[w][ci][4 * lid + 4]);
            const float4 b0 = *reinterpret_cast<const float4*>(&xs[w][ci][128 + 4 * lid]);
            const float4 b1 = *reinterpret_cast<const float4*>(&xs[w][ci][128 + 4 * lid + 4]);
            xw[0][0] = a0.x; xw[0][1] = a0.y; xw[0][2] = a0.z; xw[0][3] = a0.w;
            xw[0][4] = a1.x; xw[0][5] = a1.y; xw[0][6] = a1.z; xw[0][7] = a1.w;
            xw[1][0] = b0.x; xw[1][1] = b0.y; xw[1][2] = b0.z; xw[1][3] = b0.w;
            xw[1][4] = b1.x; xw[1][5] = b1.y; xw[1][6] = b1.z; xw[1][7] = b1.w;
        }

        #pragma unroll
        for (int j = 0; j < 2; ++j) {
            #pragma unroll
            for (int i = 0; i < 7; ++i) {
                const float2 xk = dup2(xw[j][i]);
                #pragma unroll
                for (int k = 0; k < FS; ++k) {
                    const int q = i - k;
                    if (q >= 0 && q < 4) {
                        #pragma unroll
                        for (int cp = 0; cp < 4; ++cp)
                            acc[j][q][cp] = ffma2(wv[k][cp], xk, acc[j][q][cp]);
                    }
                }
            }
        }
    }

    // ---- epilogue: warp-coalesced STG.128 per (co, bundle) ----
    float* __restrict__ ob = out + (size_t)b * COUT * L_LEN + base + 4 * lid;
    #pragma unroll
    for (int cp = 0; cp < 4; ++cp) {
        #pragma unroll
        for (int j = 0; j < 2; ++j) {
            float4 v;
            v.x = acc[j][0][cp].x; v.y = acc[j][1][cp].x;
            v.z = acc[j][2][cp].x; v.w = acc[j][3][cp].x;
            *reinterpret_cast<float4*>(ob + (size_t)(2 * cp) * L_LEN + 128 * j) = v;
            v.x = acc[j][0][cp].y; v.y = acc[j][1][cp].y;
            v.z = acc[j][2][cp].y; v.w = acc[j][3][cp].y;
            *reinterpret_cast<float4*>(ob + (size_t)(2 * cp + 1) * L_LEN + 128 * j) = v;
        }
    }
}

extern "C" void kernel_launch(void* const* d_in, const int* in_sizes, int n_in,
                              void* d_out, int out_size)
{
    const float* x    = (const float*)d_in[0];  // (64, 8, 65536)
    const float* W    = (const float*)d_in[1];  // (8, 8, 4)
    const float* bias = (const float*)d_in[2];  // (8,)
    float* out        = (float*)d_out;          // (64, 8, 65536)

    // 64 batches * 64 chunks (1024 positions, 256 per warp) = 4096 blocks
    conv_pbc_kernel<<<64 * (L_LEN / TILE), TPB>>>(x, W, bias, out);
}